// round 7
// baseline (speedup 1.0000x reference)
#include <cuda_runtime.h>
#include <cuda_fp16.h>
#include <cuda_bf16.h>
#include <math_constants.h>
#include <cstdint>
#include <cstring>

// Problem constants (fixed by reference setup_inputs)
#define BATCH   2
#define SEQ     4096
#define DMODEL  768
#define NHEADS  12
#define DHEAD   64
#define BT      (BATCH * SEQ)        // 8192
#define C3      (3 * DMODEL)         // 2304

// Scratch (device globals: allocation-free per harness rules)
__device__ float g_qkv[(size_t)BT * C3];     // [B*T, 3C]
__device__ float g_att[(size_t)BT * DMODEL]; // [B*T, C] attention output (pre-proj)

// ---------------------------------------------------------------------------
// PTX helpers
// ---------------------------------------------------------------------------
__device__ __forceinline__ float fast_exp2(float x) {
    float y;
    asm("ex2.approx.f32 %0, %1;" : "=f"(y) : "f"(x));
    return y;
}

__device__ __forceinline__ uint32_t h2_as_u32(__half2 h) {
    uint32_t r; memcpy(&r, &h, 4); return r;
}
__device__ __forceinline__ uint32_t bf2_as_u32(__nv_bfloat162 h) {
    uint32_t r; memcpy(&r, &h, 4); return r;
}

__device__ __forceinline__ void mma_f16(float c[4], const uint32_t a[4],
                                        uint32_t b0, uint32_t b1) {
    asm volatile(
        "mma.sync.aligned.m16n8k16.row.col.f32.f16.f16.f32 "
        "{%0,%1,%2,%3},{%4,%5,%6,%7},{%8,%9},{%0,%1,%2,%3};"
        : "+f"(c[0]), "+f"(c[1]), "+f"(c[2]), "+f"(c[3])
        : "r"(a[0]), "r"(a[1]), "r"(a[2]), "r"(a[3]), "r"(b0), "r"(b1));
}

__device__ __forceinline__ void mma_bf16(float c[4], const uint32_t a[4],
                                         uint32_t b0, uint32_t b1) {
    asm volatile(
        "mma.sync.aligned.m16n8k16.row.col.f32.bf16.bf16.f32 "
        "{%0,%1,%2,%3},{%4,%5,%6,%7},{%8,%9},{%0,%1,%2,%3};"
        : "+f"(c[0]), "+f"(c[1]), "+f"(c[2]), "+f"(c[3])
        : "r"(a[0]), "r"(a[1]), "r"(a[2]), "r"(a[3]), "r"(b0), "r"(b1));
}

__device__ __forceinline__ void ldmatrix_x4(uint32_t& r0, uint32_t& r1,
                                            uint32_t& r2, uint32_t& r3,
                                            uint32_t addr) {
    asm volatile(
        "ldmatrix.sync.aligned.m8n8.x4.shared.b16 {%0,%1,%2,%3}, [%4];"
        : "=r"(r0), "=r"(r1), "=r"(r2), "=r"(r3)
        : "r"(addr));
}

__device__ __forceinline__ void ldmatrix_x4_trans(uint32_t& r0, uint32_t& r1,
                                                  uint32_t& r2, uint32_t& r3,
                                                  uint32_t addr) {
    asm volatile(
        "ldmatrix.sync.aligned.m8n8.x4.trans.shared.b16 {%0,%1,%2,%3}, [%4];"
        : "=r"(r0), "=r"(r1), "=r"(r2), "=r"(r3)
        : "r"(addr));
}

// ---------------------------------------------------------------------------
// bf16x3 tensor-core GEMM: C[M,N] = A[M,K] @ B[K,N] + bias[N]  (unchanged R4)
// ---------------------------------------------------------------------------
#define GA_STRIDE 40    // halves per A smem row (32 + 8 pad)
#define GB_STRIDE 136   // halves per B smem row (128 + 8 pad)

__global__ __launch_bounds__(256)
void gemm_bf16x3_kernel(const float* __restrict__ A,
                        const float* __restrict__ B,
                        const float* __restrict__ bias,
                        float* __restrict__ Cmat,
                        int M, int N, int K)
{
    __shared__ __nv_bfloat16 Ah[128 * GA_STRIDE];
    __shared__ __nv_bfloat16 Al[128 * GA_STRIDE];
    __shared__ __nv_bfloat16 Bh[32 * GB_STRIDE];
    __shared__ __nv_bfloat16 Bl[32 * GB_STRIDE];

    const int tid  = threadIdx.x;
    const int warp = tid >> 5;
    const int lane = tid & 31;
    const int g    = lane >> 2;
    const int tg   = lane & 3;

    const int brow = blockIdx.y * 128;
    const int bcol = blockIdx.x * 128;
    const int wm   = (warp >> 2) * 64;
    const int wn   = (warp & 3) * 32;

    const uint32_t sAh = (uint32_t)__cvta_generic_to_shared(Ah);
    const uint32_t sAl = (uint32_t)__cvta_generic_to_shared(Al);
    const uint32_t sBh = (uint32_t)__cvta_generic_to_shared(Bh);
    const uint32_t sBl = (uint32_t)__cvta_generic_to_shared(Bl);

    float acc[4][4][4];
    #pragma unroll
    for (int mt = 0; mt < 4; mt++)
        #pragma unroll
        for (int nt = 0; nt < 4; nt++)
            #pragma unroll
            for (int j = 0; j < 4; j++) acc[mt][nt][j] = 0.f;

    const int n_stages = K / 32;

    float4 a_reg[4], b_reg[4];
    #pragma unroll
    for (int i = 0; i < 4; i++) {
        int idx = i * 256 + tid;
        a_reg[i] = *reinterpret_cast<const float4*>(
            &A[(size_t)(brow + (idx >> 3)) * K + (idx & 7) * 4]);
        b_reg[i] = *reinterpret_cast<const float4*>(
            &B[(size_t)(idx >> 5) * N + bcol + (idx & 31) * 4]);
    }

    for (int s = 0; s < n_stages; s++) {
        __syncthreads();
        #pragma unroll
        for (int i = 0; i < 4; i++) {
            int idx = i * 256 + tid;
            {
                float v[4] = {a_reg[i].x, a_reg[i].y, a_reg[i].z, a_reg[i].w};
                __nv_bfloat16 hi[4], lo[4];
                #pragma unroll
                for (int j = 0; j < 4; j++) {
                    hi[j] = __float2bfloat16_rn(v[j]);
                    lo[j] = __float2bfloat16_rn(v[j] - __bfloat162float(hi[j]));
                }
                int off = (idx >> 3) * GA_STRIDE + (idx & 7) * 4;
                uint2 uh, ul;
                memcpy(&uh, hi, 8); memcpy(&ul, lo, 8);
                *reinterpret_cast<uint2*>(&Ah[off]) = uh;
                *reinterpret_cast<uint2*>(&Al[off]) = ul;
            }
            {
                float v[4] = {b_reg[i].x, b_reg[i].y, b_reg[i].z, b_reg[i].w};
                __nv_bfloat16 hi[4], lo[4];
                #pragma unroll
                for (int j = 0; j < 4; j++) {
                    hi[j] = __float2bfloat16_rn(v[j]);
                    lo[j] = __float2bfloat16_rn(v[j] - __bfloat162float(hi[j]));
                }
                int off = (idx >> 5) * GB_STRIDE + (idx & 31) * 4;
                uint2 uh, ul;
                memcpy(&uh, hi, 8); memcpy(&ul, lo, 8);
                *reinterpret_cast<uint2*>(&Bh[off]) = uh;
                *reinterpret_cast<uint2*>(&Bl[off]) = ul;
            }
        }
        __syncthreads();

        if (s + 1 < n_stages) {
            int k0 = (s + 1) * 32;
            #pragma unroll
            for (int i = 0; i < 4; i++) {
                int idx = i * 256 + tid;
                a_reg[i] = *reinterpret_cast<const float4*>(
                    &A[(size_t)(brow + (idx >> 3)) * K + k0 + (idx & 7) * 4]);
                b_reg[i] = *reinterpret_cast<const float4*>(
                    &B[(size_t)(k0 + (idx >> 5)) * N + bcol + (idx & 31) * 4]);
            }
        }

        #pragma unroll
        for (int ks = 0; ks < 2; ks++) {
            uint32_t bhf[2][4], blf[2][4];
            #pragma unroll
            for (int ng = 0; ng < 2; ng++) {
                uint32_t boff = (uint32_t)(
                    (ks * 16 + (lane & 15)) * GB_STRIDE +
                    wn + ng * 16 + ((lane & 16) ? 8 : 0)) * 2u;
                ldmatrix_x4_trans(bhf[ng][0], bhf[ng][1], bhf[ng][2], bhf[ng][3],
                                  sBh + boff);
                ldmatrix_x4_trans(blf[ng][0], blf[ng][1], blf[ng][2], blf[ng][3],
                                  sBl + boff);
            }
            #pragma unroll
            for (int mt = 0; mt < 4; mt++) {
                uint32_t ahf[4], alf[4];
                uint32_t aoff = (uint32_t)(
                    (wm + mt * 16 + (lane & 15)) * GA_STRIDE +
                    ks * 16 + ((lane & 16) ? 8 : 0)) * 2u;
                ldmatrix_x4(ahf[0], ahf[1], ahf[2], ahf[3], sAh + aoff);
                ldmatrix_x4(alf[0], alf[1], alf[2], alf[3], sAl + aoff);
                #pragma unroll
                for (int ng = 0; ng < 2; ng++) {
                    #pragma unroll
                    for (int hh = 0; hh < 2; hh++) {
                        int nt = ng * 2 + hh;
                        uint32_t b0h = bhf[ng][2 * hh], b1h = bhf[ng][2 * hh + 1];
                        uint32_t b0l = blf[ng][2 * hh], b1l = blf[ng][2 * hh + 1];
                        mma_bf16(acc[mt][nt], ahf, b0h, b1h);
                        mma_bf16(acc[mt][nt], ahf, b0l, b1l);
                        mma_bf16(acc[mt][nt], alf, b0h, b1h);
                    }
                }
            }
        }
    }

    #pragma unroll
    for (int mt = 0; mt < 4; mt++) {
        #pragma unroll
        for (int nt = 0; nt < 4; nt++) {
            int row0 = brow + wm + mt * 16 + g;
            int col  = bcol + wn + nt * 8 + 2 * tg;
            float b0 = bias[col], b1 = bias[col + 1];
            float2 v0 = make_float2(acc[mt][nt][0] + b0, acc[mt][nt][1] + b1);
            float2 v1 = make_float2(acc[mt][nt][2] + b0, acc[mt][nt][3] + b1);
            *reinterpret_cast<float2*>(&Cmat[(size_t)row0 * N + col])       = v0;
            *reinterpret_cast<float2*>(&Cmat[(size_t)(row0 + 8) * N + col]) = v1;
        }
    }
}

// ---------------------------------------------------------------------------
// Tensor-core flash attention (causal), bf16x3 S-phase, natural-layout K.
// grid = (T/128, H, B), block = 256 (8 warps, 16 q-rows each -> 128-row tile).
// KV tile = 64 keys: each K/V load+convert amortized over 128 q rows.
// S = Qhi·Khi + Qhi·Klo + Qlo·Khi; base-2 online softmax; O += P·V (fp16).
// ---------------------------------------------------------------------------
#define KS 72        // halves per K smem row: 36 words % 32 == 4 -> clean
#define VSTRIDE 72   // halves per V row: ldmatrix.trans clean (validated)

__global__ __launch_bounds__(256)
void flash_attn_tc_kernel(const float* __restrict__ qkv, float* __restrict__ out)
{
    __shared__ __nv_bfloat16 Kh[64 * KS];   // K hi: [key][d]
    __shared__ __nv_bfloat16 Kl[64 * KS];   // K lo: [key][d]
    __shared__ __half        Vs[64][VSTRIDE];

    const int qt   = (int)gridDim.x - 1 - (int)blockIdx.x;  // heavy tiles first
    const int h    = blockIdx.y;
    const int b    = blockIdx.z;
    const int tid  = threadIdx.x;
    const int warp = tid >> 5;
    const int lane = tid & 31;
    const int g    = lane >> 2;
    const int tg   = lane & 3;

    const int qrow_base = qt * 128 + warp * 16;   // this warp's first q row

    const uint32_t sKh = (uint32_t)__cvta_generic_to_shared(Kh);
    const uint32_t sKl = (uint32_t)__cvta_generic_to_shared(Kl);

    // Fold softmax scale and log2(e) into Q (softmax scale-invariant).
    const float qscale = 0.125f * 1.4426950408889634f;

    // --- Q fragments, bf16 hi/lo, m16n8k16 A layout, per k16 step ---
    uint32_t qh[4][4], ql[4][4];
    {
        const float* qbase =
            qkv + (size_t)(b * SEQ + qrow_base) * C3 + h * DHEAD;
        #pragma unroll
        for (int ks = 0; ks < 4; ks++) {
            #pragma unroll
            for (int j = 0; j < 4; j++) {
                int row = g + (j & 1) * 8;
                int col = ks * 16 + 2 * tg + (j & 2) * 4;   // +8 for j=2,3
                float v0 = qbase[(size_t)row * C3 + col]     * qscale;
                float v1 = qbase[(size_t)row * C3 + col + 1] * qscale;
                __nv_bfloat16 h0 = __float2bfloat16_rn(v0);
                __nv_bfloat16 h1 = __float2bfloat16_rn(v1);
                __nv_bfloat16 l0 = __float2bfloat16_rn(v0 - __bfloat162float(h0));
                __nv_bfloat16 l1 = __float2bfloat16_rn(v1 - __bfloat162float(h1));
                qh[ks][j] = bf2_as_u32(__nv_bfloat162(h0, h1));
                ql[ks][j] = bf2_as_u32(__nv_bfloat162(l0, l1));
            }
        }
    }

    float oacc[8][4];
    #pragma unroll
    for (int dt = 0; dt < 8; dt++)
        #pragma unroll
        for (int j = 0; j < 4; j++) oacc[dt][j] = 0.f;

    float m0 = -1e30f, m1 = -1e30f, l0 = 0.f, l1 = 0.f;

    const int kt_end  = 2 * qt + 2;   // tiles 0 .. 2qt+1 (inclusive of diag)
    const int kt_diag = 2 * qt;       // masking needed from this tile on

    for (int kt = 0; kt < kt_end; kt++) {
        __syncthreads();
        // Cooperative load: K -> bf16 hi/lo [key][d] (vectorized); V -> fp16
        #pragma unroll
        for (int it = 0; it < 4; it++) {
            int idx = it * 256 + tid;       // 0..1023
            int row = idx >> 4;             // key 0..63
            int c4  = idx & 15;             // d-group 0..15
            const float* gb =
                qkv + (size_t)(b * SEQ + kt * 64 + row) * C3 + h * DHEAD;
            float4 kv = *reinterpret_cast<const float4*>(gb + DMODEL + c4 * 4);
            float kf[4] = {kv.x, kv.y, kv.z, kv.w};
            __nv_bfloat16 hi[4], lo[4];
            #pragma unroll
            for (int j = 0; j < 4; j++) {
                hi[j] = __float2bfloat16_rn(kf[j]);
                lo[j] = __float2bfloat16_rn(kf[j] - __bfloat162float(hi[j]));
            }
            uint2 uh, ul;
            memcpy(&uh, hi, 8); memcpy(&ul, lo, 8);
            *reinterpret_cast<uint2*>(&Kh[row * KS + c4 * 4]) = uh;
            *reinterpret_cast<uint2*>(&Kl[row * KS + c4 * 4]) = ul;

            float4 vv = *reinterpret_cast<const float4*>(gb + 2 * DMODEL + c4 * 4);
            __half2 p01 = __floats2half2_rn(vv.x, vv.y);
            __half2 p23 = __floats2half2_rn(vv.z, vv.w);
            *reinterpret_cast<__half2*>(&Vs[row][c4 * 4])     = p01;
            *reinterpret_cast<__half2*>(&Vs[row][c4 * 4 + 2]) = p23;
        }
        __syncthreads();

        // --- S = Qhi·Khi + Qhi·Klo + Qlo·Khi (bf16 k16 mma) ---
        float sacc[8][4];
        #pragma unroll
        for (int nt = 0; nt < 8; nt++)
            #pragma unroll
            for (int j = 0; j < 4; j++) sacc[nt][j] = 0.f;

        #pragma unroll
        for (int ks = 0; ks < 4; ks++) {
            #pragma unroll
            for (int ng = 0; ng < 4; ng++) {     // 4 key-groups of 16
                uint32_t boff = (uint32_t)(
                    (ng * 16 + (lane & 15)) * KS +
                    ks * 16 + ((lane & 16) ? 8 : 0)) * 2u;
                uint32_t bh0, bh1, bh2, bh3, bl0, bl1, bl2, bl3;
                ldmatrix_x4(bh0, bh1, bh2, bh3, sKh + boff);
                ldmatrix_x4(bl0, bl1, bl2, bl3, sKl + boff);
                mma_bf16(sacc[ng * 2],     qh[ks], bh0, bh2);
                mma_bf16(sacc[ng * 2],     qh[ks], bl0, bl2);
                mma_bf16(sacc[ng * 2],     ql[ks], bh0, bh2);
                mma_bf16(sacc[ng * 2 + 1], qh[ks], bh1, bh3);
                mma_bf16(sacc[ng * 2 + 1], qh[ks], bl1, bl3);
                mma_bf16(sacc[ng * 2 + 1], ql[ks], bh1, bh3);
            }
        }

        // --- causal mask (only near the diagonal; exact elementwise) ---
        if (kt >= kt_diag) {
            #pragma unroll
            for (int nt = 0; nt < 8; nt++) {
                #pragma unroll
                for (int j = 0; j < 4; j++) {
                    int row = qrow_base + g + (j >> 1) * 8;
                    int col = kt * 64 + nt * 8 + 2 * tg + (j & 1);
                    if (col > row) sacc[nt][j] = -1e30f;
                }
            }
        }

        // --- online softmax (base-2) ---
        float mx0 = -1e30f, mx1 = -1e30f;
        #pragma unroll
        for (int nt = 0; nt < 8; nt++) {
            mx0 = fmaxf(mx0, fmaxf(sacc[nt][0], sacc[nt][1]));
            mx1 = fmaxf(mx1, fmaxf(sacc[nt][2], sacc[nt][3]));
        }
        mx0 = fmaxf(mx0, __shfl_xor_sync(0xffffffffu, mx0, 1));
        mx0 = fmaxf(mx0, __shfl_xor_sync(0xffffffffu, mx0, 2));
        mx1 = fmaxf(mx1, __shfl_xor_sync(0xffffffffu, mx1, 1));
        mx1 = fmaxf(mx1, __shfl_xor_sync(0xffffffffu, mx1, 2));

        float mn0 = fmaxf(m0, mx0);
        float mn1 = fmaxf(m1, mx1);
        float al0 = fast_exp2(m0 - mn0);
        float al1 = fast_exp2(m1 - mn1);

        float rs0 = 0.f, rs1 = 0.f;
        #pragma unroll
        for (int nt = 0; nt < 8; nt++) {
            float p0 = fast_exp2(sacc[nt][0] - mn0);
            float p1 = fast_exp2(sacc[nt][1] - mn0);
            float p2 = fast_exp2(sacc[nt][2] - mn1);
            float p3 = fast_exp2(sacc[nt][3] - mn1);
            sacc[nt][0] = p0; sacc[nt][1] = p1;
            sacc[nt][2] = p2; sacc[nt][3] = p3;
            rs0 += p0 + p1;
            rs1 += p2 + p3;
        }
        rs0 += __shfl_xor_sync(0xffffffffu, rs0, 1);
        rs0 += __shfl_xor_sync(0xffffffffu, rs0, 2);
        rs1 += __shfl_xor_sync(0xffffffffu, rs1, 1);
        rs1 += __shfl_xor_sync(0xffffffffu, rs1, 2);

        l0 = l0 * al0 + rs0;
        l1 = l1 * al1 + rs1;
        m0 = mn0;
        m1 = mn1;

        #pragma unroll
        for (int dt = 0; dt < 8; dt++) {
            oacc[dt][0] *= al0; oacc[dt][1] *= al0;
            oacc[dt][2] *= al1; oacc[dt][3] *= al1;
        }

        // --- O += P * V  (fp16 mma; P from S accumulators in-place) ---
        #pragma unroll
        for (int ks = 0; ks < 4; ks++) {
            uint32_t pa[4];
            pa[0] = h2_as_u32(__floats2half2_rn(sacc[2*ks][0],   sacc[2*ks][1]));
            pa[1] = h2_as_u32(__floats2half2_rn(sacc[2*ks][2],   sacc[2*ks][3]));
            pa[2] = h2_as_u32(__floats2half2_rn(sacc[2*ks+1][0], sacc[2*ks+1][1]));
            pa[3] = h2_as_u32(__floats2half2_rn(sacc[2*ks+1][2], sacc[2*ks+1][3]));
            #pragma unroll
            for (int dp = 0; dp < 4; dp++) {
                int krow = ks * 16 + (lane & 15);
                int col  = dp * 16 + ((lane & 16) ? 8 : 0);
                uint32_t addr = (uint32_t)__cvta_generic_to_shared(&Vs[krow][col]);
                uint32_t b0, b1, b2, b3;
                ldmatrix_x4_trans(b0, b1, b2, b3, addr);
                mma_f16(oacc[2 * dp],     pa, b0, b1);
                mma_f16(oacc[2 * dp + 1], pa, b2, b3);
            }
        }
    }

    // --- normalize + write ---
    const float inv0 = 1.f / l0;
    const float inv1 = 1.f / l1;
    float* obase = out + (size_t)(b * SEQ + qrow_base) * DMODEL + h * DHEAD;
    #pragma unroll
    for (int dt = 0; dt < 8; dt++) {
        int col = dt * 8 + 2 * tg;
        float2 v0 = make_float2(oacc[dt][0] * inv0, oacc[dt][1] * inv0);
        float2 v1 = make_float2(oacc[dt][2] * inv1, oacc[dt][3] * inv1);
        *reinterpret_cast<float2*>(&obase[(size_t)g * DMODEL + col])       = v0;
        *reinterpret_cast<float2*>(&obase[(size_t)(g + 8) * DMODEL + col]) = v1;
    }
}

// ---------------------------------------------------------------------------
// Launch
// ---------------------------------------------------------------------------
extern "C" void kernel_launch(void* const* d_in, const int* in_sizes, int n_in,
                              void* d_out, int out_size)
{
    const float* x      = (const float*)d_in[0];
    const float* W_qkv  = (const float*)d_in[1];
    const float* b_qkv  = (const float*)d_in[2];
    const float* W_proj = (const float*)d_in[3];
    const float* b_proj = (const float*)d_in[4];
    float* out = (float*)d_out;

    void* p_qkv = nullptr;
    void* p_att = nullptr;
    cudaGetSymbolAddress(&p_qkv, g_qkv);
    cudaGetSymbolAddress(&p_att, g_att);
    float* qkv = (float*)p_qkv;
    float* att = (float*)p_att;

    // 1) QKV projection (bf16x3 tensor cores)
    {
        dim3 grid(C3 / 128, BT / 128);
        gemm_bf16x3_kernel<<<grid, 256>>>(x, W_qkv, b_qkv, qkv, BT, C3, DMODEL);
    }

    // 2) Causal flash attention per (b, h) — 128-row q-tiles, bf16x3 S, fp16 PV
    {
        dim3 grid(SEQ / 128, NHEADS, BATCH);
        flash_attn_tc_kernel<<<grid, 256>>>(qkv, att);
    }

    // 3) Output projection (bf16x3 tensor cores)
    {
        dim3 grid(DMODEL / 128, BT / 128);
        gemm_bf16x3_kernel<<<grid, 256>>>(att, W_proj, b_proj, out, BT, DMODEL, DMODEL);
    }
}

// round 8
// speedup vs baseline: 1.1792x; 1.1792x over previous
#include <cuda_runtime.h>
#include <cuda_fp16.h>
#include <cuda_bf16.h>
#include <math_constants.h>
#include <cstdint>
#include <cstring>

// Problem constants (fixed by reference setup_inputs)
#define BATCH   2
#define SEQ     4096
#define DMODEL  768
#define NHEADS  12
#define DHEAD   64
#define BT      (BATCH * SEQ)        // 8192
#define C3      (3 * DMODEL)         // 2304

// Scratch (device globals: allocation-free per harness rules)
__device__ float         g_qkv[(size_t)BT * C3];     // [B*T, 3C]
__device__ float         g_att[(size_t)BT * DMODEL]; // attention out (pre-proj)
__device__ __nv_bfloat16 g_kh[(size_t)BT * DMODEL];  // K bf16 hi
__device__ __nv_bfloat16 g_kl[(size_t)BT * DMODEL];  // K bf16 lo
__device__ __half        g_vh[(size_t)BT * DMODEL];  // V fp16

// ---------------------------------------------------------------------------
// PTX helpers
// ---------------------------------------------------------------------------
__device__ __forceinline__ float fast_exp2(float x) {
    float y;
    asm("ex2.approx.f32 %0, %1;" : "=f"(y) : "f"(x));
    return y;
}

__device__ __forceinline__ uint32_t h2_as_u32(__half2 h) {
    uint32_t r; memcpy(&r, &h, 4); return r;
}
__device__ __forceinline__ uint32_t bf2_as_u32(__nv_bfloat162 h) {
    uint32_t r; memcpy(&r, &h, 4); return r;
}

__device__ __forceinline__ void mma_f16(float c[4], const uint32_t a[4],
                                        uint32_t b0, uint32_t b1) {
    asm volatile(
        "mma.sync.aligned.m16n8k16.row.col.f32.f16.f16.f32 "
        "{%0,%1,%2,%3},{%4,%5,%6,%7},{%8,%9},{%0,%1,%2,%3};"
        : "+f"(c[0]), "+f"(c[1]), "+f"(c[2]), "+f"(c[3])
        : "r"(a[0]), "r"(a[1]), "r"(a[2]), "r"(a[3]), "r"(b0), "r"(b1));
}

__device__ __forceinline__ void mma_bf16(float c[4], const uint32_t a[4],
                                         uint32_t b0, uint32_t b1) {
    asm volatile(
        "mma.sync.aligned.m16n8k16.row.col.f32.bf16.bf16.f32 "
        "{%0,%1,%2,%3},{%4,%5,%6,%7},{%8,%9},{%0,%1,%2,%3};"
        : "+f"(c[0]), "+f"(c[1]), "+f"(c[2]), "+f"(c[3])
        : "r"(a[0]), "r"(a[1]), "r"(a[2]), "r"(a[3]), "r"(b0), "r"(b1));
}

__device__ __forceinline__ void ldmatrix_x4(uint32_t& r0, uint32_t& r1,
                                            uint32_t& r2, uint32_t& r3,
                                            uint32_t addr) {
    asm volatile(
        "ldmatrix.sync.aligned.m8n8.x4.shared.b16 {%0,%1,%2,%3}, [%4];"
        : "=r"(r0), "=r"(r1), "=r"(r2), "=r"(r3)
        : "r"(addr));
}

__device__ __forceinline__ void ldmatrix_x4_trans(uint32_t& r0, uint32_t& r1,
                                                  uint32_t& r2, uint32_t& r3,
                                                  uint32_t addr) {
    asm volatile(
        "ldmatrix.sync.aligned.m8n8.x4.trans.shared.b16 {%0,%1,%2,%3}, [%4];"
        : "=r"(r0), "=r"(r1), "=r"(r2), "=r"(r3)
        : "r"(addr));
}

// ---------------------------------------------------------------------------
// bf16x3 tensor-core GEMM: C[M,N] = A[M,K] @ B[K,N] + bias[N]  (unchanged R4)
// ---------------------------------------------------------------------------
#define GA_STRIDE 40    // halves per A smem row (32 + 8 pad)
#define GB_STRIDE 136   // halves per B smem row (128 + 8 pad)

__global__ __launch_bounds__(256)
void gemm_bf16x3_kernel(const float* __restrict__ A,
                        const float* __restrict__ B,
                        const float* __restrict__ bias,
                        float* __restrict__ Cmat,
                        int M, int N, int K)
{
    __shared__ __nv_bfloat16 Ah[128 * GA_STRIDE];
    __shared__ __nv_bfloat16 Al[128 * GA_STRIDE];
    __shared__ __nv_bfloat16 Bh[32 * GB_STRIDE];
    __shared__ __nv_bfloat16 Bl[32 * GB_STRIDE];

    const int tid  = threadIdx.x;
    const int warp = tid >> 5;
    const int lane = tid & 31;
    const int g    = lane >> 2;
    const int tg   = lane & 3;

    const int brow = blockIdx.y * 128;
    const int bcol = blockIdx.x * 128;
    const int wm   = (warp >> 2) * 64;
    const int wn   = (warp & 3) * 32;

    const uint32_t sAh = (uint32_t)__cvta_generic_to_shared(Ah);
    const uint32_t sAl = (uint32_t)__cvta_generic_to_shared(Al);
    const uint32_t sBh = (uint32_t)__cvta_generic_to_shared(Bh);
    const uint32_t sBl = (uint32_t)__cvta_generic_to_shared(Bl);

    float acc[4][4][4];
    #pragma unroll
    for (int mt = 0; mt < 4; mt++)
        #pragma unroll
        for (int nt = 0; nt < 4; nt++)
            #pragma unroll
            for (int j = 0; j < 4; j++) acc[mt][nt][j] = 0.f;

    const int n_stages = K / 32;

    float4 a_reg[4], b_reg[4];
    #pragma unroll
    for (int i = 0; i < 4; i++) {
        int idx = i * 256 + tid;
        a_reg[i] = *reinterpret_cast<const float4*>(
            &A[(size_t)(brow + (idx >> 3)) * K + (idx & 7) * 4]);
        b_reg[i] = *reinterpret_cast<const float4*>(
            &B[(size_t)(idx >> 5) * N + bcol + (idx & 31) * 4]);
    }

    for (int s = 0; s < n_stages; s++) {
        __syncthreads();
        #pragma unroll
        for (int i = 0; i < 4; i++) {
            int idx = i * 256 + tid;
            {
                float v[4] = {a_reg[i].x, a_reg[i].y, a_reg[i].z, a_reg[i].w};
                __nv_bfloat16 hi[4], lo[4];
                #pragma unroll
                for (int j = 0; j < 4; j++) {
                    hi[j] = __float2bfloat16_rn(v[j]);
                    lo[j] = __float2bfloat16_rn(v[j] - __bfloat162float(hi[j]));
                }
                int off = (idx >> 3) * GA_STRIDE + (idx & 7) * 4;
                uint2 uh, ul;
                memcpy(&uh, hi, 8); memcpy(&ul, lo, 8);
                *reinterpret_cast<uint2*>(&Ah[off]) = uh;
                *reinterpret_cast<uint2*>(&Al[off]) = ul;
            }
            {
                float v[4] = {b_reg[i].x, b_reg[i].y, b_reg[i].z, b_reg[i].w};
                __nv_bfloat16 hi[4], lo[4];
                #pragma unroll
                for (int j = 0; j < 4; j++) {
                    hi[j] = __float2bfloat16_rn(v[j]);
                    lo[j] = __float2bfloat16_rn(v[j] - __bfloat162float(hi[j]));
                }
                int off = (idx >> 5) * GB_STRIDE + (idx & 31) * 4;
                uint2 uh, ul;
                memcpy(&uh, hi, 8); memcpy(&ul, lo, 8);
                *reinterpret_cast<uint2*>(&Bh[off]) = uh;
                *reinterpret_cast<uint2*>(&Bl[off]) = ul;
            }
        }
        __syncthreads();

        if (s + 1 < n_stages) {
            int k0 = (s + 1) * 32;
            #pragma unroll
            for (int i = 0; i < 4; i++) {
                int idx = i * 256 + tid;
                a_reg[i] = *reinterpret_cast<const float4*>(
                    &A[(size_t)(brow + (idx >> 3)) * K + k0 + (idx & 7) * 4]);
                b_reg[i] = *reinterpret_cast<const float4*>(
                    &B[(size_t)(k0 + (idx >> 5)) * N + bcol + (idx & 31) * 4]);
            }
        }

        #pragma unroll
        for (int ks = 0; ks < 2; ks++) {
            uint32_t bhf[2][4], blf[2][4];
            #pragma unroll
            for (int ng = 0; ng < 2; ng++) {
                uint32_t boff = (uint32_t)(
                    (ks * 16 + (lane & 15)) * GB_STRIDE +
                    wn + ng * 16 + ((lane & 16) ? 8 : 0)) * 2u;
                ldmatrix_x4_trans(bhf[ng][0], bhf[ng][1], bhf[ng][2], bhf[ng][3],
                                  sBh + boff);
                ldmatrix_x4_trans(blf[ng][0], blf[ng][1], blf[ng][2], blf[ng][3],
                                  sBl + boff);
            }
            #pragma unroll
            for (int mt = 0; mt < 4; mt++) {
                uint32_t ahf[4], alf[4];
                uint32_t aoff = (uint32_t)(
                    (wm + mt * 16 + (lane & 15)) * GA_STRIDE +
                    ks * 16 + ((lane & 16) ? 8 : 0)) * 2u;
                ldmatrix_x4(ahf[0], ahf[1], ahf[2], ahf[3], sAh + aoff);
                ldmatrix_x4(alf[0], alf[1], alf[2], alf[3], sAl + aoff);
                #pragma unroll
                for (int ng = 0; ng < 2; ng++) {
                    #pragma unroll
                    for (int hh = 0; hh < 2; hh++) {
                        int nt = ng * 2 + hh;
                        uint32_t b0h = bhf[ng][2 * hh], b1h = bhf[ng][2 * hh + 1];
                        uint32_t b0l = blf[ng][2 * hh], b1l = blf[ng][2 * hh + 1];
                        mma_bf16(acc[mt][nt], ahf, b0h, b1h);
                        mma_bf16(acc[mt][nt], ahf, b0l, b1l);
                        mma_bf16(acc[mt][nt], alf, b0h, b1h);
                    }
                }
            }
        }
    }

    #pragma unroll
    for (int mt = 0; mt < 4; mt++) {
        #pragma unroll
        for (int nt = 0; nt < 4; nt++) {
            int row0 = brow + wm + mt * 16 + g;
            int col  = bcol + wn + nt * 8 + 2 * tg;
            float b0 = bias[col], b1 = bias[col + 1];
            float2 v0 = make_float2(acc[mt][nt][0] + b0, acc[mt][nt][1] + b1);
            float2 v1 = make_float2(acc[mt][nt][2] + b0, acc[mt][nt][3] + b1);
            *reinterpret_cast<float2*>(&Cmat[(size_t)row0 * N + col])       = v0;
            *reinterpret_cast<float2*>(&Cmat[(size_t)(row0 + 8) * N + col]) = v1;
        }
    }
}

// ---------------------------------------------------------------------------
// KV pre-convert: K fp32 -> bf16 hi/lo, V fp32 -> fp16 (streaming, once).
// One thread per float4: BT*DMODEL/4 = 1.57M threads.
// ---------------------------------------------------------------------------
__global__ __launch_bounds__(256)
void kv_convert_kernel(const float* __restrict__ qkv,
                       __nv_bfloat16* __restrict__ kh,
                       __nv_bfloat16* __restrict__ kl,
                       __half* __restrict__ vh)
{
    const int idx = blockIdx.x * 256 + threadIdx.x;     // 0 .. BT*192-1
    const int row = idx / (DMODEL / 4);
    const int c4  = idx % (DMODEL / 4);
    const size_t src = (size_t)row * C3 + c4 * 4;
    const size_t dst = (size_t)row * DMODEL + c4 * 4;

    float4 kv = *reinterpret_cast<const float4*>(&qkv[src + DMODEL]);
    float kf[4] = {kv.x, kv.y, kv.z, kv.w};
    __nv_bfloat16 hi[4], lo[4];
    #pragma unroll
    for (int j = 0; j < 4; j++) {
        hi[j] = __float2bfloat16_rn(kf[j]);
        lo[j] = __float2bfloat16_rn(kf[j] - __bfloat162float(hi[j]));
    }
    uint2 uh, ul;
    memcpy(&uh, hi, 8); memcpy(&ul, lo, 8);
    *reinterpret_cast<uint2*>(&kh[dst]) = uh;
    *reinterpret_cast<uint2*>(&kl[dst]) = ul;

    float4 vv = *reinterpret_cast<const float4*>(&qkv[src + 2 * DMODEL]);
    __half hv[4] = {__float2half_rn(vv.x), __float2half_rn(vv.y),
                    __float2half_rn(vv.z), __float2half_rn(vv.w)};
    uint2 uv;
    memcpy(&uv, hv, 8);
    *reinterpret_cast<uint2*>(&vh[dst]) = uv;
}

// ---------------------------------------------------------------------------
// Tensor-core flash attention (causal), bf16x3 S-phase, pre-converted K/V.
// grid = (T/64, H, B), block = 128 (4 warps, 16 q-rows each). KV tile = 64.
// K/V loaded as bf16/fp16 uint4 copies (no conversion in the hot loop).
// S = Qhi·Khi + Qhi·Klo + Qlo·Khi; base-2 online softmax; O += P·V (fp16).
// ---------------------------------------------------------------------------
#define KS 72        // halves per K smem row: 36 words % 32 == 4 -> clean
#define VSTRIDE 72   // halves per V row: ldmatrix.trans clean (validated)

__global__ __launch_bounds__(128)
void flash_attn_tc_kernel(const float* __restrict__ qkv,
                          const __nv_bfloat16* __restrict__ gkh,
                          const __nv_bfloat16* __restrict__ gkl,
                          const __half* __restrict__ gvh,
                          float* __restrict__ out)
{
    __shared__ __nv_bfloat16 Kh[64 * KS];   // K hi: [key][d]
    __shared__ __nv_bfloat16 Kl[64 * KS];   // K lo: [key][d]
    __shared__ __half        Vs[64][VSTRIDE];

    const int qt   = (int)gridDim.x - 1 - (int)blockIdx.x;  // heavy tiles first
    const int h    = blockIdx.y;
    const int b    = blockIdx.z;
    const int tid  = threadIdx.x;
    const int warp = tid >> 5;
    const int lane = tid & 31;
    const int g    = lane >> 2;
    const int tg   = lane & 3;

    const uint32_t sKh = (uint32_t)__cvta_generic_to_shared(Kh);
    const uint32_t sKl = (uint32_t)__cvta_generic_to_shared(Kl);

    // Fold softmax scale and log2(e) into Q (softmax scale-invariant).
    const float qscale = 0.125f * 1.4426950408889634f;

    // --- Q fragments, bf16 hi/lo, m16n8k16 A layout, per k16 step ---
    uint32_t qh[4][4], ql[4][4];
    {
        const float* qbase =
            qkv + (size_t)(b * SEQ + qt * 64 + warp * 16) * C3 + h * DHEAD;
        #pragma unroll
        for (int ks = 0; ks < 4; ks++) {
            #pragma unroll
            for (int j = 0; j < 4; j++) {
                int row = g + (j & 1) * 8;
                int col = ks * 16 + 2 * tg + (j & 2) * 4;   // +8 for j=2,3
                float v0 = qbase[(size_t)row * C3 + col]     * qscale;
                float v1 = qbase[(size_t)row * C3 + col + 1] * qscale;
                __nv_bfloat16 h0 = __float2bfloat16_rn(v0);
                __nv_bfloat16 h1 = __float2bfloat16_rn(v1);
                __nv_bfloat16 l0 = __float2bfloat16_rn(v0 - __bfloat162float(h0));
                __nv_bfloat16 l1 = __float2bfloat16_rn(v1 - __bfloat162float(h1));
                qh[ks][j] = bf2_as_u32(__nv_bfloat162(h0, h1));
                ql[ks][j] = bf2_as_u32(__nv_bfloat162(l0, l1));
            }
        }
    }

    float oacc[8][4];
    #pragma unroll
    for (int dt = 0; dt < 8; dt++)
        #pragma unroll
        for (int j = 0; j < 4; j++) oacc[dt][j] = 0.f;

    float m0 = -1e30f, m1 = -1e30f, l0 = 0.f, l1 = 0.f;

    for (int kt = 0; kt <= qt; kt++) {
        __syncthreads();
        // Cooperative copy of pre-converted K hi/lo and V into smem (uint4).
        #pragma unroll
        for (int it = 0; it < 4; it++) {
            int idx = it * 128 + tid;       // 0..511
            int row = idx >> 3;             // key 0..63
            int c8  = idx & 7;              // 8-half group 0..7
            const size_t gidx =
                (size_t)(b * SEQ + kt * 64 + row) * DMODEL + h * DHEAD + c8 * 8;
            *reinterpret_cast<uint4*>(&Kh[row * KS + c8 * 8]) =
                *reinterpret_cast<const uint4*>(&gkh[gidx]);
            *reinterpret_cast<uint4*>(&Kl[row * KS + c8 * 8]) =
                *reinterpret_cast<const uint4*>(&gkl[gidx]);
            *reinterpret_cast<uint4*>(&Vs[row][c8 * 8]) =
                *reinterpret_cast<const uint4*>(&gvh[gidx]);
        }
        __syncthreads();

        // --- S = Qhi·Khi + Qhi·Klo + Qlo·Khi (bf16 k16 mma) ---
        // ldmatrix non-trans on [key][d]: r0=(n0-7,k0-7) r1=(n8-15,k0-7)
        //                                 r2=(n0-7,k8-15) r3=(n8-15,k8-15)
        float sacc[8][4];
        #pragma unroll
        for (int nt = 0; nt < 8; nt++)
            #pragma unroll
            for (int j = 0; j < 4; j++) sacc[nt][j] = 0.f;

        #pragma unroll
        for (int ks = 0; ks < 4; ks++) {
            #pragma unroll
            for (int ng = 0; ng < 4; ng++) {     // 4 key-groups of 16
                uint32_t boff = (uint32_t)(
                    (ng * 16 + (lane & 15)) * KS +
                    ks * 16 + ((lane & 16) ? 8 : 0)) * 2u;
                uint32_t bh0, bh1, bh2, bh3, bl0, bl1, bl2, bl3;
                ldmatrix_x4(bh0, bh1, bh2, bh3, sKh + boff);
                ldmatrix_x4(bl0, bl1, bl2, bl3, sKl + boff);
                mma_bf16(sacc[ng * 2],     qh[ks], bh0, bh2);
                mma_bf16(sacc[ng * 2],     qh[ks], bl0, bl2);
                mma_bf16(sacc[ng * 2],     ql[ks], bh0, bh2);
                mma_bf16(sacc[ng * 2 + 1], qh[ks], bh1, bh3);
                mma_bf16(sacc[ng * 2 + 1], qh[ks], bl1, bl3);
                mma_bf16(sacc[ng * 2 + 1], ql[ks], bh1, bh3);
            }
        }

        // --- causal mask on diagonal tile ---
        if (kt == qt) {
            #pragma unroll
            for (int nt = 0; nt < 8; nt++) {
                #pragma unroll
                for (int j = 0; j < 4; j++) {
                    int row = warp * 16 + g + (j >> 1) * 8;
                    int col = nt * 8 + 2 * tg + (j & 1);
                    if (col > row) sacc[nt][j] = -1e30f;
                }
            }
        }

        // --- online softmax (base-2) ---
        float mx0 = -1e30f, mx1 = -1e30f;
        #pragma unroll
        for (int nt = 0; nt < 8; nt++) {
            mx0 = fmaxf(mx0, fmaxf(sacc[nt][0], sacc[nt][1]));
            mx1 = fmaxf(mx1, fmaxf(sacc[nt][2], sacc[nt][3]));
        }
        mx0 = fmaxf(mx0, __shfl_xor_sync(0xffffffffu, mx0, 1));
        mx0 = fmaxf(mx0, __shfl_xor_sync(0xffffffffu, mx0, 2));
        mx1 = fmaxf(mx1, __shfl_xor_sync(0xffffffffu, mx1, 1));
        mx1 = fmaxf(mx1, __shfl_xor_sync(0xffffffffu, mx1, 2));

        float mn0 = fmaxf(m0, mx0);
        float mn1 = fmaxf(m1, mx1);
        float al0 = fast_exp2(m0 - mn0);
        float al1 = fast_exp2(m1 - mn1);

        float rs0 = 0.f, rs1 = 0.f;
        #pragma unroll
        for (int nt = 0; nt < 8; nt++) {
            float p0 = fast_exp2(sacc[nt][0] - mn0);
            float p1 = fast_exp2(sacc[nt][1] - mn0);
            float p2 = fast_exp2(sacc[nt][2] - mn1);
            float p3 = fast_exp2(sacc[nt][3] - mn1);
            sacc[nt][0] = p0; sacc[nt][1] = p1;
            sacc[nt][2] = p2; sacc[nt][3] = p3;
            rs0 += p0 + p1;
            rs1 += p2 + p3;
        }
        rs0 += __shfl_xor_sync(0xffffffffu, rs0, 1);
        rs0 += __shfl_xor_sync(0xffffffffu, rs0, 2);
        rs1 += __shfl_xor_sync(0xffffffffu, rs1, 1);
        rs1 += __shfl_xor_sync(0xffffffffu, rs1, 2);

        l0 = l0 * al0 + rs0;
        l1 = l1 * al1 + rs1;
        m0 = mn0;
        m1 = mn1;

        #pragma unroll
        for (int dt = 0; dt < 8; dt++) {
            oacc[dt][0] *= al0; oacc[dt][1] *= al0;
            oacc[dt][2] *= al1; oacc[dt][3] *= al1;
        }

        // --- O += P * V  (fp16 mma; P from S accumulators in-place) ---
        #pragma unroll
        for (int ks = 0; ks < 4; ks++) {
            uint32_t pa[4];
            pa[0] = h2_as_u32(__floats2half2_rn(sacc[2*ks][0],   sacc[2*ks][1]));
            pa[1] = h2_as_u32(__floats2half2_rn(sacc[2*ks][2],   sacc[2*ks][3]));
            pa[2] = h2_as_u32(__floats2half2_rn(sacc[2*ks+1][0], sacc[2*ks+1][1]));
            pa[3] = h2_as_u32(__floats2half2_rn(sacc[2*ks+1][2], sacc[2*ks+1][3]));
            #pragma unroll
            for (int dp = 0; dp < 4; dp++) {
                int krow = ks * 16 + (lane & 15);
                int col  = dp * 16 + ((lane & 16) ? 8 : 0);
                uint32_t addr = (uint32_t)__cvta_generic_to_shared(&Vs[krow][col]);
                uint32_t b0, b1, b2, b3;
                ldmatrix_x4_trans(b0, b1, b2, b3, addr);
                mma_f16(oacc[2 * dp],     pa, b0, b1);
                mma_f16(oacc[2 * dp + 1], pa, b2, b3);
            }
        }
    }

    // --- normalize + write ---
    const float inv0 = 1.f / l0;
    const float inv1 = 1.f / l1;
    float* obase = out + (size_t)(b * SEQ + qt * 64 + warp * 16) * DMODEL + h * DHEAD;
    #pragma unroll
    for (int dt = 0; dt < 8; dt++) {
        int col = dt * 8 + 2 * tg;
        float2 v0 = make_float2(oacc[dt][0] * inv0, oacc[dt][1] * inv0);
        float2 v1 = make_float2(oacc[dt][2] * inv1, oacc[dt][3] * inv1);
        *reinterpret_cast<float2*>(&obase[(size_t)g * DMODEL + col])       = v0;
        *reinterpret_cast<float2*>(&obase[(size_t)(g + 8) * DMODEL + col]) = v1;
    }
}

// ---------------------------------------------------------------------------
// Launch
// ---------------------------------------------------------------------------
extern "C" void kernel_launch(void* const* d_in, const int* in_sizes, int n_in,
                              void* d_out, int out_size)
{
    const float* x      = (const float*)d_in[0];
    const float* W_qkv  = (const float*)d_in[1];
    const float* b_qkv  = (const float*)d_in[2];
    const float* W_proj = (const float*)d_in[3];
    const float* b_proj = (const float*)d_in[4];
    float* out = (float*)d_out;

    void *p_qkv = nullptr, *p_att = nullptr;
    void *p_kh = nullptr, *p_kl = nullptr, *p_vh = nullptr;
    cudaGetSymbolAddress(&p_qkv, g_qkv);
    cudaGetSymbolAddress(&p_att, g_att);
    cudaGetSymbolAddress(&p_kh, g_kh);
    cudaGetSymbolAddress(&p_kl, g_kl);
    cudaGetSymbolAddress(&p_vh, g_vh);
    float* qkv = (float*)p_qkv;
    float* att = (float*)p_att;
    __nv_bfloat16* kh = (__nv_bfloat16*)p_kh;
    __nv_bfloat16* kl = (__nv_bfloat16*)p_kl;
    __half*        vh = (__half*)p_vh;

    // 1) QKV projection (bf16x3 tensor cores)
    {
        dim3 grid(C3 / 128, BT / 128);
        gemm_bf16x3_kernel<<<grid, 256>>>(x, W_qkv, b_qkv, qkv, BT, C3, DMODEL);
    }

    // 1b) Pre-convert K -> bf16 hi/lo, V -> fp16 (streaming)
    {
        int n4 = BT * (DMODEL / 4);
        kv_convert_kernel<<<n4 / 256, 256>>>(qkv, kh, kl, vh);
    }

    // 2) Causal flash attention per (b, h) — 64-row q-tiles, pre-converted KV
    {
        dim3 grid(SEQ / 64, NHEADS, BATCH);
        flash_attn_tc_kernel<<<grid, 128>>>(qkv, kh, kl, vh, att);
    }

    // 3) Output projection (bf16x3 tensor cores)
    {
        dim3 grid(DMODEL / 128, BT / 128);
        gemm_bf16x3_kernel<<<grid, 256>>>(att, W_proj, b_proj, out, BT, DMODEL, DMODEL);
    }
}